// round 3
// baseline (speedup 1.0000x reference)
#include <cuda_runtime.h>

#define NN 32
#define RESOL 256
#define KK 1024
#define NK (NN * KK)
#define EPSF 1e-6f
#define LOG2E 1.4426950408889634f
#define LN2 0.6931471805599453f
#define MAGICF 12582912.0f  // 1.5 * 2^23, bits 0x4B400000 (low 9 bits zero)

// loss tiling: block = (n, chunk of 32 j); 256 thr = 32 j x 8 i-octants
#define CHUNKS 32
#define JPB 32
#define QUARTS 8
#define PAIRS_PER_T 64  // (KK/2 i-pairs) / QUARTS

// Scratch (__device__ globals: allocation-free rule). SoA, pre-scaled by log2e.
__device__ float g_sx[NK], g_sy[NK], g_tx[NK], g_ty[NK];
__device__ float g_loss, g_viscount;
__device__ int g_mode;
__device__ unsigned int g_done;

typedef unsigned long long ull;

__device__ __forceinline__ float sqrt_approx(float x) {
    float r; asm("sqrt.approx.f32 %0, %1;" : "=f"(r) : "f"(x)); return r;
}
__device__ __forceinline__ ull f2_add(ull a, ull b) {
    ull r; asm("add.rn.f32x2 %0, %1, %2;" : "=l"(r) : "l"(a), "l"(b)); return r;
}
__device__ __forceinline__ ull f2_mul(ull a, ull b) {
    ull r; asm("mul.rn.f32x2 %0, %1, %2;" : "=l"(r) : "l"(a), "l"(b)); return r;
}
__device__ __forceinline__ ull f2_fma(ull a, ull b, ull c) {
    ull r; asm("fma.rn.f32x2 %0, %1, %2, %3;" : "=l"(r) : "l"(a), "l"(b), "l"(c)); return r;
}
__device__ __forceinline__ ull pk_f(float lo, float hi) {
    ull r; asm("mov.b64 %0, {%1, %2};" : "=l"(r) : "f"(lo), "f"(hi)); return r;
}
__device__ __forceinline__ ull pk_u(unsigned lo, unsigned hi) {
    ull r; asm("mov.b64 %0, {%1, %2};" : "=l"(r) : "r"(lo), "r"(hi)); return r;
}
__device__ __forceinline__ void upk_f(ull a, float& lo, float& hi) {
    asm("mov.b64 {%0, %1}, %2;" : "=f"(lo), "=f"(hi) : "l"(a));
}
__device__ __forceinline__ void upk_u(ull a, unsigned& lo, unsigned& hi) {
    asm("mov.b64 {%0, %1}, %2;" : "=r"(lo), "=r"(hi) : "l"(a));
}

// ---------------------------------------------------------------------------
// Kernel A: bilinear sampling (grid_sample zeros/align_corners=True), outputs
// scaled by log2e into SoA scratch. One thread per (point, field). Block 0
// also detects kp_vis dtype and zeroes accumulators.
// ---------------------------------------------------------------------------
__device__ __forceinline__ float2 bsample(const float2* __restrict__ flow,
                                          float x, float y) {
    float x0 = floorf(x), y0 = floorf(y);
    float wx = x - x0, wy = y - y0;
    float ax = 0.0f, ay = 0.0f;
#pragma unroll
    for (int dy = 0; dy < 2; dy++) {
#pragma unroll
        for (int dx = 0; dx < 2; dx++) {
            float xi = x0 + (float)dx;
            float yi = y0 + (float)dy;
            bool valid = (xi >= 0.0f) && (xi <= (float)(RESOL - 1)) &&
                         (yi >= 0.0f) && (yi <= (float)(RESOL - 1));
            if (valid) {
                float w = (dx ? wx : 1.0f - wx) * (dy ? wy : 1.0f - wy);
                float2 v = flow[(int)yi * RESOL + (int)xi];
                ax = fmaf(w, v.x, ax);
                ay = fmaf(w, v.y, ay);
            }
        }
    }
    return make_float2(ax, ay);
}

__global__ void __launch_bounds__(256) sample_kernel(
    const float* __restrict__ src_flow, const float* __restrict__ trg_flow,
    const float* __restrict__ src_kp, const float* __restrict__ trg_kp,
    const unsigned char* __restrict__ visraw) {
    if (blockIdx.x == 0) {
        // dtype of serialized bool kp_vis from byte pattern of first 4096 bytes:
        // u8 bool -> nonzero at residue 1; f32 1.0f -> residues 2,3; i32 -> residue 0
        __shared__ int s_r1, s_r23;
        if (threadIdx.x == 0) {
            s_r1 = 0; s_r23 = 0;
            g_loss = 0.0f; g_viscount = 0.0f; g_done = 0u;
        }
        __syncthreads();
        int r1 = 0, r23 = 0;
        const int base = threadIdx.x * 16;
#pragma unroll
        for (int k = 0; k < 16; k++) {
            unsigned char b = visraw[base + k];
            if (b) {
                int r = (base + k) & 3;
                if (r == 1) r1 = 1; else if (r >= 2) r23 = 1;
            }
        }
        if (r1) atomicOr(&s_r1, 1);
        if (r23) atomicOr(&s_r23, 1);
        __syncthreads();
        if (threadIdx.x == 0) g_mode = s_r1 ? 0 : (s_r23 ? 2 : 1);
    }

    int idx = blockIdx.x * 256 + threadIdx.x;  // [0, 2*NK)
    bool is_src = idx < NK;
    int p = is_src ? idx : idx - NK;
    int n = p >> 10;
    const float* flow = is_src ? src_flow : trg_flow;
    const float* kp = is_src ? src_kp : trg_kp;
    const float2* fl = (const float2*)(flow + (size_t)n * RESOL * RESOL * 2);
    float2 k2 = ((const float2*)kp)[p];
    float2 c = bsample(fl, k2.x, k2.y);
    if (is_src) { g_sx[p] = c.x * LOG2E; g_sy[p] = c.y * LOG2E; }
    else        { g_tx[p] = c.x * LOG2E; g_ty[p] = c.y * LOG2E; }
}

// ---------------------------------------------------------------------------
// Kernel B: loss + fused finalize.
// All coords pre-scaled by log2e, so t = ||s - t' ||_scaled = d * log2e and
// exp(-d) = 2^(-t). 2^(-t) computed on the FMA pipe (packed f32x2, two pairs
// per instruction): z = t + MAGIC gives n=round(t) in mantissa bits,
// u = (z - MAGIC) - t in [-0.5, 0.5], 2^u via deg-4 poly, exponent fixed by
// integer subtract of (bits(z)<<23). Only SQRT remains on MUFU.
// loss_j = ln2 * t(j,j) + log( sum_i 2^(-t(i,j)) );  d1==d2 forward -> x2.
// ---------------------------------------------------------------------------
__global__ void __launch_bounds__(256) loss_kernel(
    const unsigned char* __restrict__ visraw,
    const float* __restrict__ kp_wt, float* __restrict__ out) {
    __shared__ float s_sx[KK], s_sy[KK];
    __shared__ float s_sum[JPB];

    const int n = blockIdx.x >> 5;
    const int chunk = blockIdx.x & 31;
    const int tid = threadIdx.x;

    ((float4*)s_sx)[tid] = ((const float4*)(g_sx + n * KK))[tid];
    ((float4*)s_sy)[tid] = ((const float4*)(g_sy + n * KK))[tid];
    if (tid < JPB) s_sum[tid] = 0.0f;
    __syncthreads();

    const int jl = tid & 31;
    const int q = tid >> 5;  // warp id = i-octant
    const int j = chunk * JPB + jl;

    const float txs = g_tx[n * KK + j];
    const float tys = g_ty[n * KK + j];
    const float ntx = EPSF * LOG2E - txs;  // dx_scaled = sxs + ntx
    const float nty = EPSF * LOG2E - tys;
    const ull ntx2 = pk_f(ntx, ntx);
    const ull nty2 = pk_f(nty, nty);
    const ull MAG2 = pk_f(MAGICF, MAGICF);
    const ull NMAG2 = pk_f(-MAGICF, -MAGICF);
    const ull NEG1 = pk_f(-1.0f, -1.0f);
    const ull C4 = pk_f(0.00961813f, 0.00961813f);
    const ull C3 = pk_f(0.05550411f, 0.05550411f);
    const ull C2 = pk_f(0.24022651f, 0.24022651f);
    const ull C1 = pk_f(0.69314718f, 0.69314718f);
    const ull C0 = pk_f(1.0f, 1.0f);

    const ull* __restrict__ sx2 = ((const ull*)s_sx) + q * PAIRS_PER_T;
    const ull* __restrict__ sy2 = ((const ull*)s_sy) + q * PAIRS_PER_T;

    ull sum2 = pk_f(0.0f, 0.0f);
#pragma unroll 8
    for (int ii = 0; ii < PAIRS_PER_T; ii++) {
        ull dx = f2_add(sx2[ii], ntx2);          // warp-uniform LDS.64 broadcast
        ull dy = f2_add(sy2[ii], nty2);
        ull ss = f2_fma(dx, dx, f2_mul(dy, dy));
        float slo, shi;
        upk_f(ss, slo, shi);
        ull t2 = pk_f(sqrt_approx(slo), sqrt_approx(shi));  // 2x MUFU.SQRT
        ull z = f2_add(t2, MAG2);                 // n = round(t) in mantissa
        ull g = f2_add(z, NMAG2);                 // g = (float)n
        ull u = f2_fma(t2, NEG1, g);              // u = n - t in [-0.5, 0.5]
        ull p = f2_fma(C4, u, C3);                // 2^u, deg-4
        p = f2_fma(p, u, C2);
        p = f2_fma(p, u, C1);
        p = f2_fma(p, u, C0);
        unsigned zlo, zhi, plo, phi;
        upk_u(z, zlo, zhi);
        upk_u(p, plo, phi);
        unsigned rlo = plo - (zlo << 23);         // * 2^(-n)
        unsigned rhi = phi - (zhi << 23);
        sum2 = f2_add(sum2, pk_u(rlo, rhi));
    }
    {
        float slo, shi;
        upk_f(sum2, slo, shi);
        atomicAdd(&s_sum[jl], slo + shi);
    }
    __syncthreads();

    if (tid < JPB) {  // one warp: jl == tid, txs/ntx already correct (q==0)
        float dx = s_sx[j] + ntx;
        float dy = s_sy[j] + nty;
        float tjj = sqrt_approx(fmaf(dx, dx, dy * dy));  // scaled diag dist

        const int jg = n * KK + j;
        const int m = g_mode;
        bool v;
        if (m == 0)      v = visraw[jg] != 0;
        else if (m == 1) v = ((const int*)visraw)[jg] != 0;
        else             v = ((const float*)visraw)[jg] != 0.0f;
        float visf = v ? 1.0f : 0.0f;

        float val = (LN2 * tjj + __logf(s_sum[tid])) * visf * kp_wt[jg];
#pragma unroll
        for (int off = 16; off; off >>= 1) {
            val  += __shfl_down_sync(0xFFFFFFFFu, val, off);
            visf += __shfl_down_sync(0xFFFFFFFFu, visf, off);
        }
        if (tid == 0) {
            atomicAdd(&g_loss, val);
            atomicAdd(&g_viscount, visf);
            __threadfence();
            unsigned int ticket = atomicAdd(&g_done, 1u);
            if (ticket == gridDim.x - 1) {
                float L = *((volatile float*)&g_loss);
                float V = *((volatile float*)&g_viscount);
                out[0] = 2.0f * L / V;
            }
        }
    }
}

extern "C" void kernel_launch(void* const* d_in, const int* in_sizes, int n_in,
                              void* d_out, int out_size) {
    (void)in_sizes; (void)n_in; (void)out_size;
    const float* src_flow = (const float*)d_in[0];
    const float* trg_flow = (const float*)d_in[1];
    const float* src_kp   = (const float*)d_in[2];
    const float* trg_kp   = (const float*)d_in[3];
    const unsigned char* kp_vis = (const unsigned char*)d_in[4];
    const float* kp_wt    = (const float*)d_in[5];
    float* out = (float*)d_out;

    sample_kernel<<<2 * NK / 256, 256>>>(src_flow, trg_flow, src_kp, trg_kp, kp_vis);
    loss_kernel<<<NN * CHUNKS, 256>>>(kp_vis, kp_wt, out);
}

// round 4
// speedup vs baseline: 1.0185x; 1.0185x over previous
#include <cuda_runtime.h>

#define NN 32
#define RESOL 256
#define KK 1024
#define NK (NN * KK)
#define EPSF 1e-6f
#define LOG2E 1.4426950408889634f
#define LN2 0.6931471805599453f
#define MAGICF 12582912.0f  // 1.5 * 2^23 (low 9 bits of encoding zero)

// loss tiling: 512 blocks = 32 n x 16 chunks; block = 64 j x 1024 i.
// 256 threads = 32 j-lanes x 8 i-octants; each thread: 64 i-pairs x 2 j.
#define CHUNKS 16
#define JPB 64
#define OCTS 8
#define PAIRS_PER_T 64  // (KK/2) / OCTS

// Scratch (__device__ globals: allocation-free rule). SoA, pre-scaled by log2e.
__device__ float g_sx[NK], g_sy[NK], g_tx[NK], g_ty[NK];
__device__ float g_loss, g_viscount;
__device__ int g_mode;
__device__ unsigned int g_done;

typedef unsigned long long ull;

__device__ __forceinline__ float sqrt_approx(float x) {
    float r; asm("sqrt.approx.f32 %0, %1;" : "=f"(r) : "f"(x)); return r;
}
__device__ __forceinline__ ull f2_add(ull a, ull b) {
    ull r; asm("add.rn.f32x2 %0, %1, %2;" : "=l"(r) : "l"(a), "l"(b)); return r;
}
__device__ __forceinline__ ull f2_mul(ull a, ull b) {
    ull r; asm("mul.rn.f32x2 %0, %1, %2;" : "=l"(r) : "l"(a), "l"(b)); return r;
}
__device__ __forceinline__ ull f2_fma(ull a, ull b, ull c) {
    ull r; asm("fma.rn.f32x2 %0, %1, %2, %3;" : "=l"(r) : "l"(a), "l"(b), "l"(c)); return r;
}
__device__ __forceinline__ ull pk_f(float lo, float hi) {
    ull r; asm("mov.b64 %0, {%1, %2};" : "=l"(r) : "f"(lo), "f"(hi)); return r;
}
__device__ __forceinline__ ull pk_u(unsigned lo, unsigned hi) {
    ull r; asm("mov.b64 %0, {%1, %2};" : "=l"(r) : "r"(lo), "r"(hi)); return r;
}
__device__ __forceinline__ void upk_f(ull a, float& lo, float& hi) {
    asm("mov.b64 {%0, %1}, %2;" : "=f"(lo), "=f"(hi) : "l"(a));
}
__device__ __forceinline__ void upk_u(ull a, unsigned& lo, unsigned& hi) {
    asm("mov.b64 {%0, %1}, %2;" : "=r"(lo), "=r"(hi) : "l"(a));
}

// ---------------------------------------------------------------------------
// Kernel A: bilinear sampling (grid_sample zeros / align_corners=True), output
// scaled by log2e into SoA scratch. One thread per (point, field). Block 0
// also detects kp_vis dtype and zeroes the accumulators.
// ---------------------------------------------------------------------------
__device__ __forceinline__ float2 bsample(const float2* __restrict__ flow,
                                          float x, float y) {
    float x0 = floorf(x), y0 = floorf(y);
    float wx = x - x0, wy = y - y0;
    float ax = 0.0f, ay = 0.0f;
#pragma unroll
    for (int dy = 0; dy < 2; dy++) {
#pragma unroll
        for (int dx = 0; dx < 2; dx++) {
            float xi = x0 + (float)dx;
            float yi = y0 + (float)dy;
            bool valid = (xi >= 0.0f) && (xi <= (float)(RESOL - 1)) &&
                         (yi >= 0.0f) && (yi <= (float)(RESOL - 1));
            if (valid) {
                float w = (dx ? wx : 1.0f - wx) * (dy ? wy : 1.0f - wy);
                float2 v = flow[(int)yi * RESOL + (int)xi];
                ax = fmaf(w, v.x, ax);
                ay = fmaf(w, v.y, ay);
            }
        }
    }
    return make_float2(ax, ay);
}

__global__ void __launch_bounds__(256) sample_kernel(
    const float* __restrict__ src_flow, const float* __restrict__ trg_flow,
    const float* __restrict__ src_kp, const float* __restrict__ trg_kp,
    const unsigned char* __restrict__ visraw) {
    if (blockIdx.x == 0) {
        // dtype of serialized bool kp_vis from byte pattern of first 4096 B:
        // u8 -> nonzero at residue 1; f32 1.0f -> residues 2,3; i32 -> residue 0
        __shared__ int s_r1, s_r23;
        if (threadIdx.x == 0) {
            s_r1 = 0; s_r23 = 0;
            g_loss = 0.0f; g_viscount = 0.0f; g_done = 0u;
        }
        __syncthreads();
        int r1 = 0, r23 = 0;
        const int base = threadIdx.x * 16;
#pragma unroll
        for (int k = 0; k < 16; k++) {
            unsigned char b = visraw[base + k];
            if (b) {
                int r = (base + k) & 3;
                if (r == 1) r1 = 1; else if (r >= 2) r23 = 1;
            }
        }
        if (r1) atomicOr(&s_r1, 1);
        if (r23) atomicOr(&s_r23, 1);
        __syncthreads();
        if (threadIdx.x == 0) g_mode = s_r1 ? 0 : (s_r23 ? 2 : 1);
    }

    int idx = blockIdx.x * 256 + threadIdx.x;  // [0, 2*NK)
    bool is_src = idx < NK;
    int p = is_src ? idx : idx - NK;
    int n = p >> 10;
    const float* flow = is_src ? src_flow : trg_flow;
    const float* kp = is_src ? src_kp : trg_kp;
    const float2* fl = (const float2*)(flow + (size_t)n * RESOL * RESOL * 2);
    float2 k2 = ((const float2*)kp)[p];
    float2 c = bsample(fl, k2.x, k2.y);
    if (is_src) { g_sx[p] = c.x * LOG2E; g_sy[p] = c.y * LOG2E; }
    else        { g_tx[p] = c.x * LOG2E; g_ty[p] = c.y * LOG2E; }
}

// ---------------------------------------------------------------------------
// Kernel B: loss + fused finalize.
// Coords pre-scaled by log2e: t = d*log2e, exp(-d) = 2^(-t), computed on the
// FMA pipe with packed f32x2 (two i's per op). Each thread handles the same
// i-pair against TWO j's (jA = base, jB = base+32) -> 2 independent chains
// and the LDS is amortized. Only SQRT stays on MUFU.
// loss_j = ln2*t(j,j) + log( sum_i 2^(-t(i,j)) );  d1==d2 forward -> x2.
// ---------------------------------------------------------------------------
__global__ void __launch_bounds__(256, 4) loss_kernel(
    const unsigned char* __restrict__ visraw,
    const float* __restrict__ kp_wt, float* __restrict__ out) {
    __shared__ float s_sx[KK], s_sy[KK];
    __shared__ float s_sum[JPB];

    const int n = blockIdx.x >> 4;        // / CHUNKS
    const int chunk = blockIdx.x & 15;    // % CHUNKS
    const int tid = threadIdx.x;

    ((float4*)s_sx)[tid] = ((const float4*)(g_sx + n * KK))[tid];
    ((float4*)s_sy)[tid] = ((const float4*)(g_sy + n * KK))[tid];
    if (tid < JPB) s_sum[tid] = 0.0f;
    __syncthreads();

    const int jl = tid & 31;
    const int q = tid >> 5;               // warp id = i-octant
    const int jA = chunk * JPB + jl;      // first j
    const int jB = jA + 32;               // second j

    const float ntxA = EPSF * LOG2E - g_tx[n * KK + jA];
    const float ntyA = EPSF * LOG2E - g_ty[n * KK + jA];
    const float ntxB = EPSF * LOG2E - g_tx[n * KK + jB];
    const float ntyB = EPSF * LOG2E - g_ty[n * KK + jB];
    const ull ntxA2 = pk_f(ntxA, ntxA), ntyA2 = pk_f(ntyA, ntyA);
    const ull ntxB2 = pk_f(ntxB, ntxB), ntyB2 = pk_f(ntyB, ntyB);
    const ull MAG2 = pk_f(MAGICF, MAGICF);
    const ull NMAG2 = pk_f(-MAGICF, -MAGICF);
    const ull NEG1 = pk_f(-1.0f, -1.0f);
    const ull C4 = pk_f(0.00961813f, 0.00961813f);
    const ull C3 = pk_f(0.05550411f, 0.05550411f);
    const ull C2 = pk_f(0.24022651f, 0.24022651f);
    const ull C1 = pk_f(0.69314718f, 0.69314718f);
    const ull C0 = pk_f(1.0f, 1.0f);

    const ull* __restrict__ sx2 = ((const ull*)s_sx) + q * PAIRS_PER_T;
    const ull* __restrict__ sy2 = ((const ull*)s_sy) + q * PAIRS_PER_T;

    ull sumA = pk_f(0.0f, 0.0f);
    ull sumB = pk_f(0.0f, 0.0f);
#pragma unroll 4
    for (int ii = 0; ii < PAIRS_PER_T; ii++) {
        const ull sx = sx2[ii];            // warp-uniform LDS.64 broadcast
        const ull sy = sy2[ii];
        // --- chain A ---
        ull dxA = f2_add(sx, ntxA2);
        ull dyA = f2_add(sy, ntyA2);
        ull ssA = f2_fma(dxA, dxA, f2_mul(dyA, dyA));
        // --- chain B ---
        ull dxB = f2_add(sx, ntxB2);
        ull dyB = f2_add(sy, ntyB2);
        ull ssB = f2_fma(dxB, dxB, f2_mul(dyB, dyB));

        float aLo, aHi, bLo, bHi;
        upk_f(ssA, aLo, aHi);
        upk_f(ssB, bLo, bHi);
        ull tA = pk_f(sqrt_approx(aLo), sqrt_approx(aHi));  // MUFU.SQRT x4
        ull tB = pk_f(sqrt_approx(bLo), sqrt_approx(bHi));

        ull zA = f2_add(tA, MAG2);          // n = round(t) in mantissa bits
        ull zB = f2_add(tB, MAG2);
        ull gA = f2_add(zA, NMAG2);         // g = (float)n
        ull gB = f2_add(zB, NMAG2);
        ull uA = f2_fma(tA, NEG1, gA);      // u = n - t in [-0.5, 0.5]
        ull uB = f2_fma(tB, NEG1, gB);
        ull pA = f2_fma(C4, uA, C3);        // 2^u, deg-4
        ull pB = f2_fma(C4, uB, C3);
        pA = f2_fma(pA, uA, C2);  pB = f2_fma(pB, uB, C2);
        pA = f2_fma(pA, uA, C1);  pB = f2_fma(pB, uB, C1);
        pA = f2_fma(pA, uA, C0);  pB = f2_fma(pB, uB, C0);

        unsigned zl, zh, pl, ph;
        upk_u(zA, zl, zh); upk_u(pA, pl, ph);
        sumA = f2_add(sumA, pk_u(pl - (zl << 23), ph - (zh << 23)));  // *2^-n
        upk_u(zB, zl, zh); upk_u(pB, pl, ph);
        sumB = f2_add(sumB, pk_u(pl - (zl << 23), ph - (zh << 23)));
    }
    {
        float lo, hi;
        upk_f(sumA, lo, hi);
        atomicAdd(&s_sum[jl], lo + hi);
        upk_f(sumB, lo, hi);
        atomicAdd(&s_sum[jl + 32], lo + hi);
    }
    __syncthreads();

    if (tid < JPB) {  // two warps, j = chunk*64 + tid
        const int j = chunk * JPB + tid;
        const int jg = n * KK + j;
        const float ntx = EPSF * LOG2E - g_tx[jg];
        const float nty = EPSF * LOG2E - g_ty[jg];
        float dx = s_sx[j] + ntx;
        float dy = s_sy[j] + nty;
        float tjj = sqrt_approx(fmaf(dx, dx, dy * dy));  // scaled diag dist

        const int m = g_mode;
        bool v;
        if (m == 0)      v = visraw[jg] != 0;
        else if (m == 1) v = ((const int*)visraw)[jg] != 0;
        else             v = ((const float*)visraw)[jg] != 0.0f;
        float visf = v ? 1.0f : 0.0f;

        float val = (LN2 * tjj + __logf(s_sum[tid])) * visf * kp_wt[jg];
#pragma unroll
        for (int off = 16; off; off >>= 1) {
            val  += __shfl_down_sync(0xFFFFFFFFu, val, off);
            visf += __shfl_down_sync(0xFFFFFFFFu, visf, off);
        }
        if ((tid & 31) == 0) {
            atomicAdd(&g_loss, val);
            atomicAdd(&g_viscount, visf);
        }
        __threadfence();
        if (tid == 0) {
            unsigned int ticket = atomicAdd(&g_done, 1u);
            if (ticket == gridDim.x - 1) {
                float L = *((volatile float*)&g_loss);
                float V = *((volatile float*)&g_viscount);
                out[0] = 2.0f * L / V;
            }
        }
    }
}

extern "C" void kernel_launch(void* const* d_in, const int* in_sizes, int n_in,
                              void* d_out, int out_size) {
    (void)in_sizes; (void)n_in; (void)out_size;
    const float* src_flow = (const float*)d_in[0];
    const float* trg_flow = (const float*)d_in[1];
    const float* src_kp   = (const float*)d_in[2];
    const float* trg_kp   = (const float*)d_in[3];
    const unsigned char* kp_vis = (const unsigned char*)d_in[4];
    const float* kp_wt    = (const float*)d_in[5];
    float* out = (float*)d_out;

    sample_kernel<<<2 * NK / 256, 256>>>(src_flow, trg_flow, src_kp, trg_kp, kp_vis);
    loss_kernel<<<NN * CHUNKS, 256>>>(kp_vis, kp_wt, out);
}